// round 1
// baseline (speedup 1.0000x reference)
#include <cuda_runtime.h>
#include <cstddef>

#define FEAT 128
#define NUM_BASES 4
#define MAX_NODES 100000

// 100000 * 512 floats = 204.8 MB scratch for basis projections
__device__ float g_proj[(size_t)MAX_NODES * NUM_BASES * FEAT];

// One GEMM: [n_nodes,128] @ [128, 640].
// Column-tiles 0..3 -> proj4 (basis b = blockIdx.y), tile 4 -> h@root + bias into d_out.
__global__ void rgcn_gemm_kernel(const float* __restrict__ h,
                                 const float* __restrict__ weight,
                                 const float* __restrict__ root_weight,
                                 const float* __restrict__ bias,
                                 float* __restrict__ out, int n_nodes)
{
    __shared__ float As[64][17];   // 64 rows x 16 k (padded)
    __shared__ float Bs[16][128];  // 16 k x 128 cols

    const int ct = blockIdx.y;
    const float* __restrict__ B = (ct < NUM_BASES) ? (weight + (size_t)ct * FEAT * FEAT)
                                                   : root_weight;
    const int row0 = blockIdx.x * 64;
    const int tid = threadIdx.x;
    const int tx = tid & 15;   // column group (8 cols each)
    const int ty = tid >> 4;   // row group (4 rows each)

    float acc[4][8];
#pragma unroll
    for (int r = 0; r < 4; r++)
#pragma unroll
        for (int c = 0; c < 8; c++) acc[r][c] = 0.f;

    for (int kc = 0; kc < FEAT; kc += 16) {
        // A tile: thread t loads row t/4, 4 floats at k = kc + (t%4)*4
        {
            int r  = tid >> 2;
            int c4 = (tid & 3) * 4;
            int grow = row0 + r;
            float4 v = make_float4(0.f, 0.f, 0.f, 0.f);
            if (grow < n_nodes)
                v = *(const float4*)(h + (size_t)grow * FEAT + kc + c4);
            As[r][c4 + 0] = v.x; As[r][c4 + 1] = v.y;
            As[r][c4 + 2] = v.z; As[r][c4 + 3] = v.w;
        }
        // B tile: thread t loads row kc + t/16, 8 floats at col (t%16)*8
        {
            int r  = tid >> 4;
            int c8 = (tid & 15) * 8;
            const float* bp = B + (size_t)(kc + r) * FEAT + c8;
            float4 v0 = *(const float4*)(bp);
            float4 v1 = *(const float4*)(bp + 4);
            *(float4*)&Bs[r][c8]     = v0;
            *(float4*)&Bs[r][c8 + 4] = v1;
        }
        __syncthreads();

#pragma unroll
        for (int kk = 0; kk < 16; kk++) {
            float a[4];
#pragma unroll
            for (int r = 0; r < 4; r++) a[r] = As[ty * 4 + r][kk];
            float b[8];
            *(float4*)&b[0] = *(const float4*)&Bs[kk][tx * 8];
            *(float4*)&b[4] = *(const float4*)&Bs[kk][tx * 8 + 4];
#pragma unroll
            for (int r = 0; r < 4; r++)
#pragma unroll
                for (int c = 0; c < 8; c++)
                    acc[r][c] = fmaf(a[r], b[c], acc[r][c]);
        }
        __syncthreads();
    }

    const int col = tx * 8;
#pragma unroll
    for (int r = 0; r < 4; r++) {
        int grow = row0 + ty * 4 + r;
        if (grow >= n_nodes) continue;
        if (ct < NUM_BASES) {
            float* p = g_proj + (size_t)grow * (NUM_BASES * FEAT) + ct * FEAT + col;
#pragma unroll
            for (int c = 0; c < 8; c++) p[c] = acc[r][c];
        } else {
            float* p = out + (size_t)grow * FEAT + col;
#pragma unroll
            for (int c = 0; c < 8; c++) p[c] = acc[r][c] + bias[col + c];
        }
    }
}

// One warp per edge: msg = sum_b w_comp[rel,b] * proj4[src, b, :]; atomic add to out[dst].
__global__ void rgcn_edge_kernel(const float* __restrict__ w_comp,
                                 const int* __restrict__ src,
                                 const int* __restrict__ dst,
                                 const int* __restrict__ rel,
                                 float* __restrict__ out, int n_edges)
{
    const int warp = (blockIdx.x * blockDim.x + threadIdx.x) >> 5;
    const int lane = threadIdx.x & 31;
    if (warp >= n_edges) return;

    const int s = src[warp];
    const int d = dst[warp];
    const int r = rel[warp];
    const float4 c = *(const float4*)(w_comp + r * NUM_BASES);

    const float* __restrict__ p = g_proj + (size_t)s * (NUM_BASES * FEAT);
    float* __restrict__ o = out + (size_t)d * FEAT;

#pragma unroll
    for (int j = 0; j < 4; j++) {
        const int i = lane + j * 32;
        float m = c.x * p[i]
                + c.y * p[FEAT + i]
                + c.z * p[2 * FEAT + i]
                + c.w * p[3 * FEAT + i];
        atomicAdd(o + i, m);
    }
}

__global__ void rgcn_relu_kernel(float* __restrict__ out, int n4)
{
    int i = blockIdx.x * blockDim.x + threadIdx.x;
    if (i < n4) {
        float4 v = ((float4*)out)[i];
        v.x = fmaxf(v.x, 0.f); v.y = fmaxf(v.y, 0.f);
        v.z = fmaxf(v.z, 0.f); v.w = fmaxf(v.w, 0.f);
        ((float4*)out)[i] = v;
    }
}

extern "C" void kernel_launch(void* const* d_in, const int* in_sizes, int n_in,
                              void* d_out, int out_size)
{
    const float* h      = (const float*)d_in[0];
    const float* weight = (const float*)d_in[1];
    const float* w_comp = (const float*)d_in[2];
    const float* root   = (const float*)d_in[3];
    const float* bias   = (const float*)d_in[4];
    const int*   src    = (const int*)d_in[5];
    const int*   dst    = (const int*)d_in[6];
    const int*   rel    = (const int*)d_in[7];

    const int n_nodes = in_sizes[0] / FEAT;
    const int n_edges = in_sizes[5];
    float* out = (float*)d_out;

    // GEMM: basis projections + root projection (+bias) fused
    dim3 g1((n_nodes + 63) / 64, NUM_BASES + 1);
    rgcn_gemm_kernel<<<g1, 256>>>(h, weight, root, bias, out, n_nodes);

    // Edge gather + combine + scatter-add
    int blocks_e = (n_edges + 7) / 8;   // 8 warps (edges) per 256-thread block
    rgcn_edge_kernel<<<blocks_e, 256>>>(w_comp, src, dst, rel, out, n_edges);

    // ReLU in place
    int n4 = out_size / 4;
    rgcn_relu_kernel<<<(n4 + 255) / 256, 256>>>(out, n4);
}